// round 14
// baseline (speedup 1.0000x reference)
#include <cuda_runtime.h>
#include <cuda_fp16.h>
#include <cstdint>
#include <cstddef>

// ---------------------------------------------------------------------------
// Bidirectional GRU, B=4096 T=16 I=H=1024.   (R11 champion + gate v2)
//   Gx = X @ [W_izr; W_it]^T   (one big GEMM, shared by both directions)
//   then two independent direction chains on two forked streams (lockstep).
// GEMM: fp16 in/out (fp32 accum), mma.sync.m16n8k16 + ldmatrix.x4 + cp.async,
// 128x128 tile, 4 warps (64x64), BK=64, 3 stages, 2 CTAs/SM.
// Gate v2: 8 hidden units per thread (uint4 fp16 loads), high MLP.
// Streams/events are created once (static) to keep the mem baseline clean.
// ---------------------------------------------------------------------------

namespace {
constexpr int B_ = 4096, T_ = 16, H_ = 1024;
constexpr int N3 = 3 * H_, K_ = 1024;
constexpr int BM = 128, BN = 128, BK = 64;   // CTA tile; BK in halfs
constexpr int NKT = K_ / BK;                 // 16 k-iterations
constexpr int NST = 3;                       // cp.async stages
constexpr int ROWB = 144;                    // smem row pitch (128B data + 16B pad)
constexpr int A_BYTES = BM * ROWB;           // 18432
constexpr int STAGE = 2 * A_BYTES;           // 36864 (A + B)
constexpr int SMEM_BYTES = NST * STAGE;      // 110592
}

// scratch (static device allocations; no runtime alloc allowed)
__device__ __align__(256) __half g_gx16[(size_t)B_ * T_ * N3];  // x-projections (fp16)
__device__ __align__(256) __half g_gh16[(size_t)2 * B_ * N3];   // h-projections (fp16)
__device__ __align__(256) float  g_h0 [(size_t)2 * B_ * H_];    // fp32 initial h per dir
__device__ __align__(256) __half g_h16[(size_t)4 * B_ * H_];    // fp16 h ping-pong (GEMM A)
__device__ __align__(256) __half g_x16[(size_t)B_ * T_ * K_];   // fp16 x
__device__ __align__(256) __half g_wx16[(size_t)N3 * K_];       // [W_izr; W_it] fp16
__device__ __align__(256) __half g_wh16[(size_t)N3 * K_];       // [W_hzr; W_ht] fp16

// ------------------------------ PTX helpers --------------------------------
__device__ __forceinline__ uint32_t smem_u32(const void* p) {
    uint32_t a;
    asm("{.reg .u64 t; cvta.to.shared.u64 t, %1; cvt.u32.u64 %0, t;}" : "=r"(a) : "l"(p));
    return a;
}
__device__ __forceinline__ void cp16(uint32_t d, const void* s) {
    asm volatile("cp.async.cg.shared.global [%0], [%1], 16;" :: "r"(d), "l"(s));
}
__device__ __forceinline__ void cp_commit() { asm volatile("cp.async.commit_group;"); }
template <int N>
__device__ __forceinline__ void cp_wait() { asm volatile("cp.async.wait_group %0;" :: "n"(N)); }

__device__ __forceinline__ void ldsm4(uint32_t& r0, uint32_t& r1, uint32_t& r2, uint32_t& r3,
                                      uint32_t a) {
    asm volatile("ldmatrix.sync.aligned.m8n8.x4.shared.b16 {%0,%1,%2,%3}, [%4];"
                 : "=r"(r0), "=r"(r1), "=r"(r2), "=r"(r3) : "r"(a));
}
__device__ __forceinline__ void mma16816(float c[4], const uint32_t a[4], const uint32_t b[2]) {
    asm volatile(
        "mma.sync.aligned.m16n8k16.row.col.f32.f16.f16.f32 "
        "{%0,%1,%2,%3},{%4,%5,%6,%7},{%8,%9},{%0,%1,%2,%3};"
        : "+f"(c[0]), "+f"(c[1]), "+f"(c[2]), "+f"(c[3])
        : "r"(a[0]), "r"(a[1]), "r"(a[2]), "r"(a[3]), "r"(b[0]), "r"(b[1]));
}
__device__ __forceinline__ float sigmoidf_(float x) { return 1.f / (1.f + expf(-x)); }

// ------------------------------ GEMM kernel --------------------------------
// recur=0: A = g_x16 (rows mb..), C = g_gx16.
// recur=1: A = g_h16[(dir*2+phase)], C = g_gh16[dir].
__global__ __launch_bounds__(128, 2)
void gemm_f16(int dir, int phase, int recur)
{
    extern __shared__ __align__(128) char smem[];
    const uint32_t sb = smem_u32(smem);
    const int tid = threadIdx.x, warp = tid >> 5, lane = tid & 31;
    const int n0 = blockIdx.x * BN, mb = blockIdx.y * BM;

    const __half* A = recur ? g_h16 + (size_t)((dir * 2 + phase) * B_ + mb) * K_
                            : g_x16 + (size_t)mb * K_;
    const __half* W = (recur ? g_wh16 : g_wx16) + (size_t)n0 * K_;
    __half* C = recur ? g_gh16 + (size_t)dir * B_ * N3 : g_gx16;

    // warp tile: 64 x 64  (warp grid 2 x 2)
    const int wm = (warp & 1) * 64, wn = (warp >> 1) * 64;
    const uint32_t aFrag = sb + (uint32_t)(wm + (lane & 15)) * ROWB + ((lane >> 4) & 1) * 16;
    const uint32_t bFrag = sb + A_BYTES +
        (uint32_t)(wn + ((lane >> 4) & 1) * 8 + (lane & 7)) * ROWB + ((lane >> 3) & 1) * 16;

    float acc[4][8][4];
#pragma unroll
    for (int a = 0; a < 4; ++a)
#pragma unroll
        for (int b = 0; b < 8; ++b)
#pragma unroll
            for (int c = 0; c < 4; ++c) acc[a][b][c] = 0.f;

#define FILL(S, KT)                                                           \
    {                                                                         \
        _Pragma("unroll")                                                     \
        for (int i = 0; i < 8; ++i) {                                         \
            int c = tid + 128 * i;                                            \
            int row = c >> 3, col = c & 7;                                    \
            uint32_t d = sb + (S) * STAGE + row * ROWB + col * 16;            \
            cp16(d, A + (size_t)row * K_ + (KT) * BK + col * 8);              \
            cp16(d + A_BYTES, W + (size_t)row * K_ + (KT) * BK + col * 8);    \
        }                                                                     \
    }

#pragma unroll
    for (int s = 0; s < NST - 1; ++s) { FILL(s, s); cp_commit(); }

    int st = 0;
    for (int kt = 0; kt < NKT; ++kt) {
        cp_wait<NST - 2>();
        __syncthreads();
        if (kt + NST - 1 < NKT) {
            int fs = st + 2; if (fs >= NST) fs -= NST;
            FILL(fs, kt + NST - 1);
        }
        cp_commit();

        const uint32_t aS = aFrag + st * STAGE;
        const uint32_t bS = bFrag + st * STAGE;
#pragma unroll
        for (int ks = 0; ks < 4; ++ks) {
            uint32_t af[4][4], bf[8][2];
#pragma unroll
            for (int mi = 0; mi < 4; ++mi)
                ldsm4(af[mi][0], af[mi][1], af[mi][2], af[mi][3],
                      aS + mi * 16 * ROWB + ks * 32);
#pragma unroll
            for (int nj = 0; nj < 4; ++nj)
                ldsm4(bf[2 * nj][0], bf[2 * nj][1], bf[2 * nj + 1][0], bf[2 * nj + 1][1],
                      bS + nj * 16 * ROWB + ks * 32);
#pragma unroll
            for (int mi = 0; mi < 4; ++mi)
#pragma unroll
                for (int ni = 0; ni < 8; ++ni)
                    mma16816(acc[mi][ni], af[mi], bf[ni]);
        }
        if (++st == NST) st = 0;
    }
#undef FILL

    __half* crow = C + (size_t)(mb + wm + (lane >> 2)) * N3 + n0 + wn + (lane & 3) * 2;
#pragma unroll
    for (int mi = 0; mi < 4; ++mi) {
#pragma unroll
        for (int ni = 0; ni < 8; ++ni) {
            *reinterpret_cast<__half2*>(crow + (size_t)(mi * 16) * N3 + ni * 8) =
                __floats2half2_rn(acc[mi][ni][0], acc[mi][ni][1]);
            *reinterpret_cast<__half2*>(crow + (size_t)(mi * 16 + 8) * N3 + ni * 8) =
                __floats2half2_rn(acc[mi][ni][2], acc[mi][ni][3]);
        }
    }
}

// --------------------------- gate kernel (v2: 8-wide) -----------------------
__global__ __launch_bounds__(256)
void gate_kernel(const float* __restrict__ b_izr, const float* __restrict__ b_hzr,
                 const float* __restrict__ b_it,  const float* __restrict__ b_ht,
                 float* __restrict__ out, int d, int s)
{
    const int idx = blockIdx.x * blockDim.x + threadIdx.x;   // B*H/8 threads
    const int j8  = idx << 3;
    const int b   = j8 >> 10;
    const int j   = j8 & (H_ - 1);
    const int time = (d == 0) ? s : (T_ - 1 - s);
    const int tout = (d == 0) ? (T_ - 1 - s) : s;

    const __half* gx = g_gx16 + ((size_t)b * T_ + time) * N3;
    const __half* gh = g_gh16 + (size_t)d * B_ * N3 + (size_t)b * N3;

    // previous fp32 h: from init at s=0, else from out written at step s-1
    float4 h0v, h1v;
    if (s == 0) {
        const float* hp = g_h0 + (size_t)d * B_ * H_ + (size_t)b * H_ + j;
        h0v = *(const float4*)(hp);
        h1v = *(const float4*)(hp + 4);
    } else {
        const int tprev = (d == 0) ? (T_ - s) : (s - 1);
        const float* hp = out + ((size_t)b * T_ + tprev) * (2 * H_) + (size_t)d * H_ + j;
        h0v = *(const float4*)(hp);
        h1v = *(const float4*)(hp + 4);
    }

    // 8-wide fp16 loads
    uint4 uxr = *(const uint4*)(gx + j);
    uint4 uxz = *(const uint4*)(gx + H_ + j);
    uint4 uxt = *(const uint4*)(gx + 2 * H_ + j);
    uint4 uhr = *(const uint4*)(gh + j);
    uint4 uhz = *(const uint4*)(gh + H_ + j);
    uint4 uht = *(const uint4*)(gh + 2 * H_ + j);
    float4 bir0 = *(const float4*)(b_izr + j),        bir1 = *(const float4*)(b_izr + j + 4);
    float4 biz0 = *(const float4*)(b_izr + H_ + j),   biz1 = *(const float4*)(b_izr + H_ + j + 4);
    float4 bhr0 = *(const float4*)(b_hzr + j),        bhr1 = *(const float4*)(b_hzr + j + 4);
    float4 bhz0 = *(const float4*)(b_hzr + H_ + j),   bhz1 = *(const float4*)(b_hzr + H_ + j + 4);
    float4 bti0 = *(const float4*)(b_it + j),         bti1 = *(const float4*)(b_it + j + 4);
    float4 bth0 = *(const float4*)(b_ht + j),         bth1 = *(const float4*)(b_ht + j + 4);

    float xr[8], xz[8], xt[8], hr[8], hz[8], ht[8];
    {
        const uint32_t* pxr = &uxr.x; const uint32_t* pxz = &uxz.x;
        const uint32_t* pxt = &uxt.x; const uint32_t* phr = &uhr.x;
        const uint32_t* phz = &uhz.x; const uint32_t* pht = &uht.x;
#pragma unroll
        for (int q = 0; q < 4; ++q) {
            float2 t;
            t = __half22float2(*reinterpret_cast<const __half2*>(pxr + q)); xr[2*q] = t.x; xr[2*q+1] = t.y;
            t = __half22float2(*reinterpret_cast<const __half2*>(pxz + q)); xz[2*q] = t.x; xz[2*q+1] = t.y;
            t = __half22float2(*reinterpret_cast<const __half2*>(pxt + q)); xt[2*q] = t.x; xt[2*q+1] = t.y;
            t = __half22float2(*reinterpret_cast<const __half2*>(phr + q)); hr[2*q] = t.x; hr[2*q+1] = t.y;
            t = __half22float2(*reinterpret_cast<const __half2*>(phz + q)); hz[2*q] = t.x; hz[2*q+1] = t.y;
            t = __half22float2(*reinterpret_cast<const __half2*>(pht + q)); ht[2*q] = t.x; ht[2*q+1] = t.y;
        }
    }
    float bir[8] = {bir0.x, bir0.y, bir0.z, bir0.w, bir1.x, bir1.y, bir1.z, bir1.w};
    float biz[8] = {biz0.x, biz0.y, biz0.z, biz0.w, biz1.x, biz1.y, biz1.z, biz1.w};
    float bhr[8] = {bhr0.x, bhr0.y, bhr0.z, bhr0.w, bhr1.x, bhr1.y, bhr1.z, bhr1.w};
    float bhz[8] = {bhz0.x, bhz0.y, bhz0.z, bhz0.w, bhz1.x, bhz1.y, bhz1.z, bhz1.w};
    float bti[8] = {bti0.x, bti0.y, bti0.z, bti0.w, bti1.x, bti1.y, bti1.z, bti1.w};
    float bth[8] = {bth0.x, bth0.y, bth0.z, bth0.w, bth1.x, bth1.y, bth1.z, bth1.w};
    float hv[8]  = {h0v.x, h0v.y, h0v.z, h0v.w, h1v.x, h1v.y, h1v.z, h1v.w};

    float nh[8];
#pragma unroll
    for (int q = 0; q < 8; ++q) {
        float rg = sigmoidf_(xr[q] + hr[q] + bir[q] + bhr[q]);
        float zg = sigmoidf_(xz[q] + hz[q] + biz[q] + bhz[q]);
        float tg = tanhf(xt[q] + bti[q] + rg * (ht[q] + bth[q]));
        nh[q] = zg * tg + (1.f - zg) * hv[q];
    }

    // stores: fp16 mirror (uint4) + fp32 out (2x float4)
    uint4 u16;
    {
        __half2 p0 = __floats2half2_rn(nh[0], nh[1]);
        __half2 p1 = __floats2half2_rn(nh[2], nh[3]);
        __half2 p2 = __floats2half2_rn(nh[4], nh[5]);
        __half2 p3 = __floats2half2_rn(nh[6], nh[7]);
        u16.x = *reinterpret_cast<uint32_t*>(&p0);
        u16.y = *reinterpret_cast<uint32_t*>(&p1);
        u16.z = *reinterpret_cast<uint32_t*>(&p2);
        u16.w = *reinterpret_cast<uint32_t*>(&p3);
    }
    const size_t hoff = ((size_t)d * 2 + ((s + 1) & 1)) * B_ * H_ + (size_t)b * H_ + j;
    *reinterpret_cast<uint4*>(g_h16 + hoff) = u16;
    float* op = out + ((size_t)b * T_ + tout) * (2 * H_) + (size_t)d * H_ + j;
    *(float4*)(op)     = make_float4(nh[0], nh[1], nh[2], nh[3]);
    *(float4*)(op + 4) = make_float4(nh[4], nh[5], nh[6], nh[7]);
}

// ------------------------------ small kernels ------------------------------
__global__ void cvt16(const float* __restrict__ s, __half* __restrict__ d, int n4)
{
    int i = blockIdx.x * blockDim.x + threadIdx.x;
    if (i < n4) {
        float4 v = reinterpret_cast<const float4*>(s)[i];
        __half2 p0 = __floats2half2_rn(v.x, v.y);
        __half2 p1 = __floats2half2_rn(v.z, v.w);
        uint2 u; u.x = *reinterpret_cast<uint32_t*>(&p0); u.y = *reinterpret_cast<uint32_t*>(&p1);
        reinterpret_cast<uint2*>(d)[i] = u;
    }
}

__global__ void init_h(const float* __restrict__ h0, const float* __restrict__ bih0)
{
    size_t i = (size_t)blockIdx.x * blockDim.x + threadIdx.x;
    if (i < (size_t)B_ * H_) {
        float a = h0[i], b = bih0[i];
        g_h0[i] = a;
        g_h0[(size_t)B_ * H_ + i] = b;
        g_h16[i] = __float2half_rn(a);                       // dir 0, phase 0
        g_h16[(size_t)2 * B_ * H_ + i] = __float2half_rn(b); // dir 1, phase 0
    }
}

// ------------------------------ host side ----------------------------------
extern "C" void kernel_launch(void* const* d_in, const int* in_sizes, int n_in,
                              void* d_out, int out_size)
{
    const float* x     = (const float*)d_in[0];
    const float* h0    = (const float*)d_in[1];
    const float* bih0  = (const float*)d_in[2];
    const float* W_izr = (const float*)d_in[3];
    const float* b_izr = (const float*)d_in[4];
    const float* W_hzr = (const float*)d_in[5];
    const float* b_hzr = (const float*)d_in[6];
    const float* W_it  = (const float*)d_in[7];
    const float* b_it  = (const float*)d_in[8];
    const float* W_ht  = (const float*)d_in[9];
    const float* b_ht  = (const float*)d_in[10];
    float* out = (float*)d_out;
    (void)in_sizes; (void)n_in; (void)out_size;

    void *p_x16 = nullptr, *p_wx = nullptr, *p_wh = nullptr;
    cudaGetSymbolAddress(&p_x16, g_x16);
    cudaGetSymbolAddress(&p_wx, g_wx16);
    cudaGetSymbolAddress(&p_wh, g_wh16);

    cudaFuncSetAttribute(gemm_f16, cudaFuncAttributeMaxDynamicSharedMemorySize, SMEM_BYTES);

    // streams/events created ONCE (deterministic; keeps mem baseline stable)
    static cudaStream_t st2 = nullptr;
    static cudaEvent_t evFork, evPrep2, evGx, evJoin;
    if (st2 == nullptr) {
        cudaStreamCreateWithFlags(&st2, cudaStreamNonBlocking);
        cudaEventCreateWithFlags(&evFork,  cudaEventDisableTiming);
        cudaEventCreateWithFlags(&evPrep2, cudaEventDisableTiming);
        cudaEventCreateWithFlags(&evGx,    cudaEventDisableTiming);
        cudaEventCreateWithFlags(&evJoin,  cudaEventDisableTiming);
    }

    cudaEventRecord(evFork, 0);
    cudaStreamWaitEvent(st2, evFork, 0);

    // prep split across streams
    const int WN4 = 2 * H_ * K_ / 4, WN4b = H_ * K_ / 4, XN4 = B_ * T_ * K_ / 4;
    cvt16<<<(WN4 + 255) / 256, 256>>>(W_izr, (__half*)p_wx, WN4);
    cvt16<<<(WN4b + 255) / 256, 256>>>(W_it, (__half*)p_wx + (size_t)2 * H_ * K_, WN4b);
    cvt16<<<(XN4 + 255) / 256, 256>>>(x, (__half*)p_x16, XN4);
    cvt16<<<(WN4 + 255) / 256, 256, 0, st2>>>(W_hzr, (__half*)p_wh, WN4);
    cvt16<<<(WN4b + 255) / 256, 256, 0, st2>>>(W_ht, (__half*)p_wh + (size_t)2 * H_ * K_, WN4b);
    init_h<<<(B_ * H_ + 255) / 256, 256, 0, st2>>>(h0, bih0);
    cudaEventRecord(evPrep2, st2);

    // Gx = X @ [W_izr; W_it]^T over all (b, t)   (stream 0)
    gemm_f16<<<dim3(N3 / BN, (B_ * T_) / BM), 128, SMEM_BYTES>>>(0, 0, 0);
    cudaEventRecord(evGx, 0);

    // stream 0's chain needs wh16/h16 (prep on st2); st2's chain needs Gx
    cudaStreamWaitEvent(0, evPrep2, 0);
    cudaStreamWaitEvent(st2, evGx, 0);

    const int GATE_BLKS = (B_ * H_) / (256 * 8);
    for (int s = 0; s < T_; ++s) {
        gemm_f16<<<dim3(N3 / BN, B_ / BM), 128, SMEM_BYTES>>>(0, s & 1, 1);
        gemm_f16<<<dim3(N3 / BN, B_ / BM), 128, SMEM_BYTES, st2>>>(1, s & 1, 1);
        gate_kernel<<<GATE_BLKS, 256>>>(b_izr, b_hzr, b_it, b_ht, out, 0, s);
        gate_kernel<<<GATE_BLKS, 256, 0, st2>>>(b_izr, b_hzr, b_it, b_ht, out, 1, s);
    }

    // join st2 back into the captured stream
    cudaEventRecord(evJoin, st2);
    cudaStreamWaitEvent(0, evJoin, 0);
}

// round 15
// speedup vs baseline: 1.5325x; 1.5325x over previous
#include <cuda_runtime.h>
#include <cuda_fp16.h>
#include <cstdint>
#include <cstddef>

// ---------------------------------------------------------------------------
// Bidirectional GRU, B=4096 T=16 I=H=1024.
// Two free-running direction chains on two streams, DE-PHASED by an
// asymmetric Gx prefix (stream0: 5 time-pair chunks, stream2: 3), so each
// chain's DRAM-bound gate window overlaps the other chain's tensor-bound
// GEMM body. GEMMs are never serialized against each other.
// Gx layout [t][b][3H] (verified in R13). GEMM: fp16 in/out (fp32 accum),
// mma.sync.m16n8k16 + ldmatrix.x4 + cp.async, 128x128 tile, 4 warps (64x64),
// BK=64, 3 stages, 2 CTAs/SM. Gate v1 (4-wide, proven). Static stream/events.
// ---------------------------------------------------------------------------

namespace {
constexpr int B_ = 4096, T_ = 16, H_ = 1024;
constexpr int N3 = 3 * H_, K_ = 1024;
constexpr int BM = 128, BN = 128, BK = 64;   // CTA tile; BK in halfs
constexpr int NKT = K_ / BK;                 // 16 k-iterations
constexpr int NST = 3;                       // cp.async stages
constexpr int ROWB = 144;                    // smem row pitch (128B data + 16B pad)
constexpr int A_BYTES = BM * ROWB;           // 18432
constexpr int STAGE = 2 * A_BYTES;           // 36864 (A + B)
constexpr int SMEM_BYTES = NST * STAGE;      // 110592
}

// scratch (static device allocations; no runtime alloc allowed)
__device__ __align__(256) __half g_gx16[(size_t)B_ * T_ * N3];  // [t][b][3H] fp16
__device__ __align__(256) __half g_gh16[(size_t)2 * B_ * N3];   // h-projections (fp16)
__device__ __align__(256) float  g_h0 [(size_t)2 * B_ * H_];    // fp32 initial h per dir
__device__ __align__(256) __half g_h16[(size_t)4 * B_ * H_];    // fp16 h ping-pong (GEMM A)
__device__ __align__(256) __half g_x16[(size_t)B_ * T_ * K_];   // fp16 x, [T][B][K]
__device__ __align__(256) __half g_wx16[(size_t)N3 * K_];       // [W_izr; W_it] fp16
__device__ __align__(256) __half g_wh16[(size_t)N3 * K_];       // [W_hzr; W_ht] fp16

// ------------------------------ PTX helpers --------------------------------
__device__ __forceinline__ uint32_t smem_u32(const void* p) {
    uint32_t a;
    asm("{.reg .u64 t; cvta.to.shared.u64 t, %1; cvt.u32.u64 %0, t;}" : "=r"(a) : "l"(p));
    return a;
}
__device__ __forceinline__ void cp16(uint32_t d, const void* s) {
    asm volatile("cp.async.cg.shared.global [%0], [%1], 16;" :: "r"(d), "l"(s));
}
__device__ __forceinline__ void cp_commit() { asm volatile("cp.async.commit_group;"); }
template <int N>
__device__ __forceinline__ void cp_wait() { asm volatile("cp.async.wait_group %0;" :: "n"(N)); }

__device__ __forceinline__ void ldsm4(uint32_t& r0, uint32_t& r1, uint32_t& r2, uint32_t& r3,
                                      uint32_t a) {
    asm volatile("ldmatrix.sync.aligned.m8n8.x4.shared.b16 {%0,%1,%2,%3}, [%4];"
                 : "=r"(r0), "=r"(r1), "=r"(r2), "=r"(r3) : "r"(a));
}
__device__ __forceinline__ void mma16816(float c[4], const uint32_t a[4], const uint32_t b[2]) {
    asm volatile(
        "mma.sync.aligned.m16n8k16.row.col.f32.f16.f16.f32 "
        "{%0,%1,%2,%3},{%4,%5,%6,%7},{%8,%9},{%0,%1,%2,%3};"
        : "+f"(c[0]), "+f"(c[1]), "+f"(c[2]), "+f"(c[3])
        : "r"(a[0]), "r"(a[1]), "r"(a[2]), "r"(a[3]), "r"(b[0]), "r"(b[1]));
}
__device__ __forceinline__ float sigmoidf_(float x) { return 1.f / (1.f + expf(-x)); }

// --------------------------- shared GEMM mainloop ---------------------------
__device__ __forceinline__ void gemm_body(const __half* __restrict__ A,
                                          const __half* __restrict__ W,
                                          __half* __restrict__ Crow0)
{
    extern __shared__ __align__(128) char smem[];
    const uint32_t sb = smem_u32(smem);
    const int tid = threadIdx.x, warp = tid >> 5, lane = tid & 31;

    const int wm = (warp & 1) * 64, wn = (warp >> 1) * 64;
    const uint32_t aFrag = sb + (uint32_t)(wm + (lane & 15)) * ROWB + ((lane >> 4) & 1) * 16;
    const uint32_t bFrag = sb + A_BYTES +
        (uint32_t)(wn + ((lane >> 4) & 1) * 8 + (lane & 7)) * ROWB + ((lane >> 3) & 1) * 16;

    float acc[4][8][4];
#pragma unroll
    for (int a = 0; a < 4; ++a)
#pragma unroll
        for (int b = 0; b < 8; ++b)
#pragma unroll
            for (int c = 0; c < 4; ++c) acc[a][b][c] = 0.f;

#define FILL(S, KT)                                                           \
    {                                                                         \
        _Pragma("unroll")                                                     \
        for (int i = 0; i < 8; ++i) {                                         \
            int c = tid + 128 * i;                                            \
            int row = c >> 3, col = c & 7;                                    \
            uint32_t d = sb + (S) * STAGE + row * ROWB + col * 16;            \
            cp16(d, A + (size_t)row * K_ + (KT) * BK + col * 8);              \
            cp16(d + A_BYTES, W + (size_t)row * K_ + (KT) * BK + col * 8);    \
        }                                                                     \
    }

#pragma unroll
    for (int s = 0; s < NST - 1; ++s) { FILL(s, s); cp_commit(); }

    int st = 0;
    for (int kt = 0; kt < NKT; ++kt) {
        cp_wait<NST - 2>();
        __syncthreads();
        if (kt + NST - 1 < NKT) {
            int fs = st + 2; if (fs >= NST) fs -= NST;
            FILL(fs, kt + NST - 1);
        }
        cp_commit();

        const uint32_t aS = aFrag + st * STAGE;
        const uint32_t bS = bFrag + st * STAGE;
#pragma unroll
        for (int ks = 0; ks < 4; ++ks) {
            uint32_t af[4][4], bf[8][2];
#pragma unroll
            for (int mi = 0; mi < 4; ++mi)
                ldsm4(af[mi][0], af[mi][1], af[mi][2], af[mi][3],
                      aS + mi * 16 * ROWB + ks * 32);
#pragma unroll
            for (int nj = 0; nj < 4; ++nj)
                ldsm4(bf[2 * nj][0], bf[2 * nj][1], bf[2 * nj + 1][0], bf[2 * nj + 1][1],
                      bS + nj * 16 * ROWB + ks * 32);
#pragma unroll
            for (int mi = 0; mi < 4; ++mi)
#pragma unroll
                for (int ni = 0; ni < 8; ++ni)
                    mma16816(acc[mi][ni], af[mi], bf[ni]);
        }
        if (++st == NST) st = 0;
    }
#undef FILL

    __half* crow = Crow0 + (size_t)(wm + (lane >> 2)) * N3 + wn + (lane & 3) * 2;
#pragma unroll
    for (int mi = 0; mi < 4; ++mi) {
#pragma unroll
        for (int ni = 0; ni < 8; ++ni) {
            *reinterpret_cast<__half2*>(crow + (size_t)(mi * 16) * N3 + ni * 8) =
                __floats2half2_rn(acc[mi][ni][0], acc[mi][ni][1]);
            *reinterpret_cast<__half2*>(crow + (size_t)(mi * 16 + 8) * N3 + ni * 8) =
                __floats2half2_rn(acc[mi][ni][2], acc[mi][ni][3]);
        }
    }
}

// recurrent step GEMM: A = g_h16[(dir*2+phase)], C = g_gh16[dir]
__global__ __launch_bounds__(128, 2)
void gemm_step(int dir, int phase)
{
    const int n0 = blockIdx.x * BN, mb = blockIdx.y * BM;
    gemm_body(g_h16 + (size_t)((dir * 2 + phase) * B_ + mb) * K_,
              g_wh16 + (size_t)n0 * K_,
              g_gh16 + (size_t)dir * B_ * N3 + (size_t)mb * N3 + n0);
}

// Gx chunk GEMM for time pair {p, 15-p}; blockIdx.y in [0,64)
__global__ __launch_bounds__(128, 2)
void gemm_gx(int p)
{
    const int n0 = blockIdx.x * BN;
    const int by = blockIdx.y;
    const int t  = (by < 32) ? p : (T_ - 1 - p);
    const int mb = t * B_ + (by & 31) * BM;
    gemm_body(g_x16 + (size_t)mb * K_,
              g_wx16 + (size_t)n0 * K_,
              g_gx16 + (size_t)mb * N3 + n0);
}

// --------------------------- gate kernel (v1) -------------------------------
__global__ __launch_bounds__(256)
void gate_kernel(const float* __restrict__ b_izr, const float* __restrict__ b_hzr,
                 const float* __restrict__ b_it,  const float* __restrict__ b_ht,
                 float* __restrict__ out, int d, int s)
{
    const int idx = blockIdx.x * blockDim.x + threadIdx.x;
    const int j4  = idx << 2;
    const int b   = j4 >> 10;
    const int j   = j4 & (H_ - 1);
    const int time = (d == 0) ? s : (T_ - 1 - s);
    const int tout = (d == 0) ? (T_ - 1 - s) : s;

    const __half* gx = g_gx16 + ((size_t)time * B_ + b) * N3;   // [t][b][3H]
    const __half* gh = g_gh16 + (size_t)d * B_ * N3 + (size_t)b * N3;

    float4 h;
    if (s == 0) {
        h = *(const float4*)(g_h0 + (size_t)d * B_ * H_ + (size_t)b * H_ + j);
    } else {
        const int tprev = (d == 0) ? (T_ - s) : (s - 1);
        h = *(const float4*)(out + ((size_t)b * T_ + tprev) * (2 * H_) +
                             (size_t)d * H_ + j);
    }
    const size_t hoff = ((size_t)d * 2 + ((s + 1) & 1)) * B_ * H_ + (size_t)b * H_ + j;

    uint2 uxr = *(const uint2*)(gx + j);
    uint2 uxz = *(const uint2*)(gx + H_ + j);
    uint2 uxt = *(const uint2*)(gx + 2 * H_ + j);
    uint2 uhr = *(const uint2*)(gh + j);
    uint2 uhz = *(const uint2*)(gh + H_ + j);
    uint2 uht = *(const uint2*)(gh + 2 * H_ + j);
    float4 bir = *(const float4*)(b_izr + j);
    float4 biz = *(const float4*)(b_izr + H_ + j);
    float4 bhr = *(const float4*)(b_hzr + j);
    float4 bhz = *(const float4*)(b_hzr + H_ + j);
    float4 bti = *(const float4*)(b_it + j);
    float4 bth = *(const float4*)(b_ht + j);

    float2 xr0 = __half22float2(*reinterpret_cast<__half2*>(&uxr.x));
    float2 xr1 = __half22float2(*reinterpret_cast<__half2*>(&uxr.y));
    float2 xz0 = __half22float2(*reinterpret_cast<__half2*>(&uxz.x));
    float2 xz1 = __half22float2(*reinterpret_cast<__half2*>(&uxz.y));
    float2 xt0 = __half22float2(*reinterpret_cast<__half2*>(&uxt.x));
    float2 xt1 = __half22float2(*reinterpret_cast<__half2*>(&uxt.y));
    float2 hr0 = __half22float2(*reinterpret_cast<__half2*>(&uhr.x));
    float2 hr1 = __half22float2(*reinterpret_cast<__half2*>(&uhr.y));
    float2 hz0 = __half22float2(*reinterpret_cast<__half2*>(&uhz.x));
    float2 hz1 = __half22float2(*reinterpret_cast<__half2*>(&uhz.y));
    float2 ht0 = __half22float2(*reinterpret_cast<__half2*>(&uht.x));
    float2 ht1 = __half22float2(*reinterpret_cast<__half2*>(&uht.y));

    float4 nh;
#define GATE(c, GXR, GHR, GXZ, GHZ, GXT, GHT)                               \
    {                                                                       \
        float rg = sigmoidf_(GXR + GHR + bir.c + bhr.c);                    \
        float zg = sigmoidf_(GXZ + GHZ + biz.c + bhz.c);                    \
        float ht = tanhf(GXT + bti.c + rg * (GHT + bth.c));                 \
        nh.c = zg * ht + (1.f - zg) * h.c;                                  \
    }
    GATE(x, xr0.x, hr0.x, xz0.x, hz0.x, xt0.x, ht0.x)
    GATE(y, xr0.y, hr0.y, xz0.y, hz0.y, xt0.y, ht0.y)
    GATE(z, xr1.x, hr1.x, xz1.x, hz1.x, xt1.x, ht1.x)
    GATE(w, xr1.y, hr1.y, xz1.y, hz1.y, xt1.y, ht1.y)
#undef GATE

    __half2 p0 = __floats2half2_rn(nh.x, nh.y);
    __half2 p1 = __floats2half2_rn(nh.z, nh.w);
    uint2 u; u.x = *reinterpret_cast<uint32_t*>(&p0); u.y = *reinterpret_cast<uint32_t*>(&p1);
    *reinterpret_cast<uint2*>(g_h16 + hoff) = u;
    *(float4*)(out + ((size_t)b * T_ + tout) * (2 * H_) + (size_t)d * H_ + j) = nh;
}

// ------------------------------ small kernels ------------------------------
__global__ void cvt16(const float* __restrict__ s, __half* __restrict__ d, int n4)
{
    int i = blockIdx.x * blockDim.x + threadIdx.x;
    if (i < n4) {
        float4 v = reinterpret_cast<const float4*>(s)[i];
        __half2 p0 = __floats2half2_rn(v.x, v.y);
        __half2 p1 = __floats2half2_rn(v.z, v.w);
        uint2 u; u.x = *reinterpret_cast<uint32_t*>(&p0); u.y = *reinterpret_cast<uint32_t*>(&p1);
        reinterpret_cast<uint2*>(d)[i] = u;
    }
}

// x [B][T][K] fp32 -> x16 [T][B][K] fp16
__global__ void cvt16x(const float* __restrict__ s, __half* __restrict__ d, int n4)
{
    int i = blockIdx.x * blockDim.x + threadIdx.x;
    if (i < n4) {
        const int KP = K_ / 4;
        int row = i / KP, col = i - row * KP;
        int b = row >> 4, t = row & (T_ - 1);
        float4 v = reinterpret_cast<const float4*>(s)[i];
        __half2 p0 = __floats2half2_rn(v.x, v.y);
        __half2 p1 = __floats2half2_rn(v.z, v.w);
        uint2 u; u.x = *reinterpret_cast<uint32_t*>(&p0); u.y = *reinterpret_cast<uint32_t*>(&p1);
        reinterpret_cast<uint2*>(d)[(size_t)(t * B_ + b) * KP + col] = u;
    }
}

__global__ void init_h(const float* __restrict__ h0, const float* __restrict__ bih0)
{
    size_t i = (size_t)blockIdx.x * blockDim.x + threadIdx.x;
    if (i < (size_t)B_ * H_) {
        float a = h0[i], b = bih0[i];
        g_h0[i] = a;
        g_h0[(size_t)B_ * H_ + i] = b;
        g_h16[i] = __float2half_rn(a);                       // dir 0, phase 0
        g_h16[(size_t)2 * B_ * H_ + i] = __float2half_rn(b); // dir 1, phase 0
    }
}

// ------------------------------ host side ----------------------------------
extern "C" void kernel_launch(void* const* d_in, const int* in_sizes, int n_in,
                              void* d_out, int out_size)
{
    const float* x     = (const float*)d_in[0];
    const float* h0    = (const float*)d_in[1];
    const float* bih0  = (const float*)d_in[2];
    const float* W_izr = (const float*)d_in[3];
    const float* b_izr = (const float*)d_in[4];
    const float* W_hzr = (const float*)d_in[5];
    const float* b_hzr = (const float*)d_in[6];
    const float* W_it  = (const float*)d_in[7];
    const float* b_it  = (const float*)d_in[8];
    const float* W_ht  = (const float*)d_in[9];
    const float* b_ht  = (const float*)d_in[10];
    float* out = (float*)d_out;
    (void)in_sizes; (void)n_in; (void)out_size;

    void *p_x16 = nullptr, *p_wx = nullptr, *p_wh = nullptr;
    cudaGetSymbolAddress(&p_x16, g_x16);
    cudaGetSymbolAddress(&p_wx, g_wx16);
    cudaGetSymbolAddress(&p_wh, g_wh16);

    cudaFuncSetAttribute(gemm_step, cudaFuncAttributeMaxDynamicSharedMemorySize, SMEM_BYTES);
    cudaFuncSetAttribute(gemm_gx,   cudaFuncAttributeMaxDynamicSharedMemorySize, SMEM_BYTES);

    // static resources (created once) — keeps device-mem baseline stable
    static cudaStream_t st2 = nullptr;
    static cudaEvent_t evFork, evPrep0, evH, evJoin;
    static cudaEvent_t gxEv[8];
    if (st2 == nullptr) {
        cudaStreamCreateWithFlags(&st2, cudaStreamNonBlocking);
        cudaEventCreateWithFlags(&evFork,  cudaEventDisableTiming);
        cudaEventCreateWithFlags(&evPrep0, cudaEventDisableTiming);
        cudaEventCreateWithFlags(&evH,     cudaEventDisableTiming);
        cudaEventCreateWithFlags(&evJoin,  cudaEventDisableTiming);
        for (int p = 0; p < 8; ++p)
            cudaEventCreateWithFlags(&gxEv[p], cudaEventDisableTiming);
    }

    cudaEventRecord(evFork, 0);
    cudaStreamWaitEvent(st2, evFork, 0);

    const int WN4 = 2 * H_ * K_ / 4, WN4b = H_ * K_ / 4, XN4 = B_ * T_ * K_ / 4;

    // stream 0: all weight conversions + x transpose (shared inputs)
    cvt16<<<(WN4 + 255) / 256, 256>>>(W_hzr, (__half*)p_wh, WN4);
    cvt16<<<(WN4b + 255) / 256, 256>>>(W_ht, (__half*)p_wh + (size_t)2 * H_ * K_, WN4b);
    cvt16<<<(WN4 + 255) / 256, 256>>>(W_izr, (__half*)p_wx, WN4);
    cvt16<<<(WN4b + 255) / 256, 256>>>(W_it, (__half*)p_wx + (size_t)2 * H_ * K_, WN4b);
    cvt16x<<<(XN4 + 255) / 256, 256>>>(x, (__half*)p_x16, XN4);
    cudaEventRecord(evPrep0, 0);

    // st2: h init, then wait for prep before its Gx chunks
    init_h<<<(B_ * H_ + 255) / 256, 256, 0, st2>>>(h0, bih0);
    cudaEventRecord(evH, st2);
    cudaStreamWaitEvent(st2, evPrep0, 0);

    // asymmetric Gx split: stream0 pairs 0..4 (5 chunks), st2 pairs 5..7 (3)
    for (int p = 0; p < 5; ++p) {
        gemm_gx<<<dim3(N3 / BN, 64), 128, SMEM_BYTES>>>(p);
        cudaEventRecord(gxEv[p], 0);
    }
    for (int p = 5; p < 8; ++p) {
        gemm_gx<<<dim3(N3 / BN, 64), 128, SMEM_BYTES, st2>>>(p);
        cudaEventRecord(gxEv[p], st2);
    }

    // chain0 (stream 0) needs h init from st2
    cudaStreamWaitEvent(0, evH, 0);

    const int GATE_BLKS = (B_ * H_) / (256 * 4);
    for (int s = 0; s < T_; ++s) {
        const int q = (s < T_ - 1 - s) ? s : (T_ - 1 - s);
        gemm_step<<<dim3(N3 / BN, B_ / BM), 128, SMEM_BYTES>>>(0, s & 1);
        gemm_step<<<dim3(N3 / BN, B_ / BM), 128, SMEM_BYTES, st2>>>(1, s & 1);
        cudaStreamWaitEvent(0, gxEv[q], 0);
        cudaStreamWaitEvent(st2, gxEv[q], 0);
        gate_kernel<<<GATE_BLKS, 256>>>(b_izr, b_hzr, b_it, b_ht, out, 0, s);
        gate_kernel<<<GATE_BLKS, 256, 0, st2>>>(b_izr, b_hzr, b_it, b_ht, out, 1, s);
    }

    // join st2 back into the captured stream
    cudaEventRecord(evJoin, st2);
    cudaStreamWaitEvent(0, evJoin, 0);
}

// round 16
// speedup vs baseline: 1.5782x; 1.0298x over previous
#include <cuda_runtime.h>
#include <cuda_fp16.h>
#include <cstdint>
#include <cstddef>

// ---------------------------------------------------------------------------
// Bidirectional GRU, B=4096 T=16 I=H=1024.   (R11 champion skeleton)
//   Gx = X @ [W_izr; W_it]^T   (one big GEMM, shared by both directions)
//   then two independent direction chains on two forked streams (lockstep).
// GEMM: fp16 in/out (fp32 accum), mma.sync.m16n8k16 + ldmatrix.x4 + cp.async,
// 128x128 tile, 4 warps (64x64), BK=64, 3 stages, 2 CTAs/SM.
// Gate v3: 8 hidden units/thread, all named scalars (no spill), prev-h read
// from the fp16 mirror (no fp32 out re-read), pre-combined biases.
// Streams/events created once (static) — keeps the mem baseline clean.
// ---------------------------------------------------------------------------

namespace {
constexpr int B_ = 4096, T_ = 16, H_ = 1024;
constexpr int N3 = 3 * H_, K_ = 1024;
constexpr int BM = 128, BN = 128, BK = 64;   // CTA tile; BK in halfs
constexpr int NKT = K_ / BK;                 // 16 k-iterations
constexpr int NST = 3;                       // cp.async stages
constexpr int ROWB = 144;                    // smem row pitch (128B data + 16B pad)
constexpr int A_BYTES = BM * ROWB;           // 18432
constexpr int STAGE = 2 * A_BYTES;           // 36864 (A + B)
constexpr int SMEM_BYTES = NST * STAGE;      // 110592
}

// scratch (static device allocations; no runtime alloc allowed)
__device__ __align__(256) __half g_gx16[(size_t)B_ * T_ * N3];  // x-projections (fp16)
__device__ __align__(256) __half g_gh16[(size_t)2 * B_ * N3];   // h-projections (fp16)
__device__ __align__(256) __half g_h16[(size_t)4 * B_ * H_];    // fp16 h ping-pong
__device__ __align__(256) __half g_x16[(size_t)B_ * T_ * K_];   // fp16 x
__device__ __align__(256) __half g_wx16[(size_t)N3 * K_];       // [W_izr; W_it] fp16
__device__ __align__(256) __half g_wh16[(size_t)N3 * K_];       // [W_hzr; W_ht] fp16
__device__ __align__(256) float  g_br[H_], g_bz[H_], g_bti[H_], g_bth[H_];

// ------------------------------ PTX helpers --------------------------------
__device__ __forceinline__ uint32_t smem_u32(const void* p) {
    uint32_t a;
    asm("{.reg .u64 t; cvta.to.shared.u64 t, %1; cvt.u32.u64 %0, t;}" : "=r"(a) : "l"(p));
    return a;
}
__device__ __forceinline__ void cp16(uint32_t d, const void* s) {
    asm volatile("cp.async.cg.shared.global [%0], [%1], 16;" :: "r"(d), "l"(s));
}
__device__ __forceinline__ void cp_commit() { asm volatile("cp.async.commit_group;"); }
template <int N>
__device__ __forceinline__ void cp_wait() { asm volatile("cp.async.wait_group %0;" :: "n"(N)); }

__device__ __forceinline__ void ldsm4(uint32_t& r0, uint32_t& r1, uint32_t& r2, uint32_t& r3,
                                      uint32_t a) {
    asm volatile("ldmatrix.sync.aligned.m8n8.x4.shared.b16 {%0,%1,%2,%3}, [%4];"
                 : "=r"(r0), "=r"(r1), "=r"(r2), "=r"(r3) : "r"(a));
}
__device__ __forceinline__ void mma16816(float c[4], const uint32_t a[4], const uint32_t b[2]) {
    asm volatile(
        "mma.sync.aligned.m16n8k16.row.col.f32.f16.f16.f32 "
        "{%0,%1,%2,%3},{%4,%5,%6,%7},{%8,%9},{%0,%1,%2,%3};"
        : "+f"(c[0]), "+f"(c[1]), "+f"(c[2]), "+f"(c[3])
        : "r"(a[0]), "r"(a[1]), "r"(a[2]), "r"(a[3]), "r"(b[0]), "r"(b[1]));
}
__device__ __forceinline__ float sigmoidf_(float x) { return 1.f / (1.f + expf(-x)); }

// ------------------------------ GEMM kernel --------------------------------
// recur=0: A = g_x16 (rows mb..), C = g_gx16.
// recur=1: A = g_h16[(dir*2+phase)], C = g_gh16[dir].
__global__ __launch_bounds__(128, 2)
void gemm_f16(int dir, int phase, int recur)
{
    extern __shared__ __align__(128) char smem[];
    const uint32_t sb = smem_u32(smem);
    const int tid = threadIdx.x, warp = tid >> 5, lane = tid & 31;
    const int n0 = blockIdx.x * BN, mb = blockIdx.y * BM;

    const __half* A = recur ? g_h16 + (size_t)((dir * 2 + phase) * B_ + mb) * K_
                            : g_x16 + (size_t)mb * K_;
    const __half* W = (recur ? g_wh16 : g_wx16) + (size_t)n0 * K_;
    __half* C = recur ? g_gh16 + (size_t)dir * B_ * N3 : g_gx16;

    // warp tile: 64 x 64  (warp grid 2 x 2)
    const int wm = (warp & 1) * 64, wn = (warp >> 1) * 64;
    const uint32_t aFrag = sb + (uint32_t)(wm + (lane & 15)) * ROWB + ((lane >> 4) & 1) * 16;
    const uint32_t bFrag = sb + A_BYTES +
        (uint32_t)(wn + ((lane >> 4) & 1) * 8 + (lane & 7)) * ROWB + ((lane >> 3) & 1) * 16;

    float acc[4][8][4];
#pragma unroll
    for (int a = 0; a < 4; ++a)
#pragma unroll
        for (int b = 0; b < 8; ++b)
#pragma unroll
            for (int c = 0; c < 4; ++c) acc[a][b][c] = 0.f;

#define FILL(S, KT)                                                           \
    {                                                                         \
        _Pragma("unroll")                                                     \
        for (int i = 0; i < 8; ++i) {                                         \
            int c = tid + 128 * i;                                            \
            int row = c >> 3, col = c & 7;                                    \
            uint32_t d = sb + (S) * STAGE + row * ROWB + col * 16;            \
            cp16(d, A + (size_t)row * K_ + (KT) * BK + col * 8);              \
            cp16(d + A_BYTES, W + (size_t)row * K_ + (KT) * BK + col * 8);    \
        }                                                                     \
    }

#pragma unroll
    for (int s = 0; s < NST - 1; ++s) { FILL(s, s); cp_commit(); }

    int st = 0;
    for (int kt = 0; kt < NKT; ++kt) {
        cp_wait<NST - 2>();
        __syncthreads();
        if (kt + NST - 1 < NKT) {
            int fs = st + 2; if (fs >= NST) fs -= NST;
            FILL(fs, kt + NST - 1);
        }
        cp_commit();

        const uint32_t aS = aFrag + st * STAGE;
        const uint32_t bS = bFrag + st * STAGE;
#pragma unroll
        for (int ks = 0; ks < 4; ++ks) {
            uint32_t af[4][4], bf[8][2];
#pragma unroll
            for (int mi = 0; mi < 4; ++mi)
                ldsm4(af[mi][0], af[mi][1], af[mi][2], af[mi][3],
                      aS + mi * 16 * ROWB + ks * 32);
#pragma unroll
            for (int nj = 0; nj < 4; ++nj)
                ldsm4(bf[2 * nj][0], bf[2 * nj][1], bf[2 * nj + 1][0], bf[2 * nj + 1][1],
                      bS + nj * 16 * ROWB + ks * 32);
#pragma unroll
            for (int mi = 0; mi < 4; ++mi)
#pragma unroll
                for (int ni = 0; ni < 8; ++ni)
                    mma16816(acc[mi][ni], af[mi], bf[ni]);
        }
        if (++st == NST) st = 0;
    }
#undef FILL

    __half* crow = C + (size_t)(mb + wm + (lane >> 2)) * N3 + n0 + wn + (lane & 3) * 2;
#pragma unroll
    for (int mi = 0; mi < 4; ++mi) {
#pragma unroll
        for (int ni = 0; ni < 8; ++ni) {
            *reinterpret_cast<__half2*>(crow + (size_t)(mi * 16) * N3 + ni * 8) =
                __floats2half2_rn(acc[mi][ni][0], acc[mi][ni][1]);
            *reinterpret_cast<__half2*>(crow + (size_t)(mi * 16 + 8) * N3 + ni * 8) =
                __floats2half2_rn(acc[mi][ni][2], acc[mi][ni][3]);
        }
    }
}

// ------------------- gate kernel v3 (8-wide, spill-free) --------------------
__global__ __launch_bounds__(256)
void gate_kernel(float* __restrict__ out, int d, int s)
{
    const int idx = blockIdx.x * blockDim.x + threadIdx.x;   // B*H/8 threads
    const int j8  = idx << 3;
    const int b   = j8 >> 10;
    const int j   = j8 & (H_ - 1);
    const int time = (d == 0) ? s : (T_ - 1 - s);
    const int tout = (d == 0) ? (T_ - 1 - s) : s;

    const __half* gx = g_gx16 + ((size_t)b * T_ + time) * N3 + j;
    const __half* gh = g_gh16 + (size_t)d * B_ * N3 + (size_t)b * N3 + j;
    const size_t hprev = ((size_t)d * 2 + (s & 1)) * B_ * H_ + (size_t)b * H_ + j;
    const size_t hnext = ((size_t)d * 2 + ((s + 1) & 1)) * B_ * H_ + (size_t)b * H_ + j;

    uint4 uxr = *(const uint4*)(gx);
    uint4 uxz = *(const uint4*)(gx + H_);
    uint4 uxt = *(const uint4*)(gx + 2 * H_);
    uint4 uhr = *(const uint4*)(gh);
    uint4 uhz = *(const uint4*)(gh + H_);
    uint4 uht = *(const uint4*)(gh + 2 * H_);
    uint4 uhp = *(const uint4*)(g_h16 + hprev);
    float4 br0 = *(const float4*)(g_br + j),  br1 = *(const float4*)(g_br + j + 4);
    float4 bz0 = *(const float4*)(g_bz + j),  bz1 = *(const float4*)(g_bz + j + 4);
    float4 bi0 = *(const float4*)(g_bti + j), bi1 = *(const float4*)(g_bti + j + 4);
    float4 bh0 = *(const float4*)(g_bth + j), bh1 = *(const float4*)(g_bth + j + 4);

#define F2(u) __half22float2(*reinterpret_cast<__half2*>(&(u)))
    float2 xr0 = F2(uxr.x), xr1 = F2(uxr.y), xr2 = F2(uxr.z), xr3 = F2(uxr.w);
    float2 xz0 = F2(uxz.x), xz1 = F2(uxz.y), xz2 = F2(uxz.z), xz3 = F2(uxz.w);
    float2 xt0 = F2(uxt.x), xt1 = F2(uxt.y), xt2 = F2(uxt.z), xt3 = F2(uxt.w);
    float2 hr0 = F2(uhr.x), hr1 = F2(uhr.y), hr2 = F2(uhr.z), hr3 = F2(uhr.w);
    float2 hz0 = F2(uhz.x), hz1 = F2(uhz.y), hz2 = F2(uhz.z), hz3 = F2(uhz.w);
    float2 ht0 = F2(uht.x), ht1 = F2(uht.y), ht2 = F2(uht.z), ht3 = F2(uht.w);
    float2 hp0 = F2(uhp.x), hp1 = F2(uhp.y), hp2 = F2(uhp.z), hp3 = F2(uhp.w);
#undef F2

    float nh0, nh1, nh2, nh3, nh4, nh5, nh6, nh7;
#define GATE(NH, XR, HR, XZ, HZ, XT, HT, BR, BZ, BI, BH, HV)                \
    {                                                                       \
        float rg = sigmoidf_((XR) + (HR) + (BR));                           \
        float zg = sigmoidf_((XZ) + (HZ) + (BZ));                           \
        float tg = tanhf((XT) + (BI) + rg * ((HT) + (BH)));                 \
        NH = zg * tg + (1.f - zg) * (HV);                                   \
    }
    GATE(nh0, xr0.x, hr0.x, xz0.x, hz0.x, xt0.x, ht0.x, br0.x, bz0.x, bi0.x, bh0.x, hp0.x)
    GATE(nh1, xr0.y, hr0.y, xz0.y, hz0.y, xt0.y, ht0.y, br0.y, bz0.y, bi0.y, bh0.y, hp0.y)
    GATE(nh2, xr1.x, hr1.x, xz1.x, hz1.x, xt1.x, ht1.x, br0.z, bz0.z, bi0.z, bh0.z, hp1.x)
    GATE(nh3, xr1.y, hr1.y, xz1.y, hz1.y, xt1.y, ht1.y, br0.w, bz0.w, bi0.w, bh0.w, hp1.y)
    GATE(nh4, xr2.x, hr2.x, xz2.x, hz2.x, xt2.x, ht2.x, br1.x, bz1.x, bi1.x, bh1.x, hp2.x)
    GATE(nh5, xr2.y, hr2.y, xz2.y, hz2.y, xt2.y, ht2.y, br1.y, bz1.y, bi1.y, bh1.y, hp2.y)
    GATE(nh6, xr3.x, hr3.x, xz3.x, hz3.x, xt3.x, ht3.x, br1.z, bz1.z, bi1.z, bh1.z, hp3.x)
    GATE(nh7, xr3.y, hr3.y, xz3.y, hz3.y, xt3.y, ht3.y, br1.w, bz1.w, bi1.w, bh1.w, hp3.y)
#undef GATE

    __half2 p0 = __floats2half2_rn(nh0, nh1);
    __half2 p1 = __floats2half2_rn(nh2, nh3);
    __half2 p2 = __floats2half2_rn(nh4, nh5);
    __half2 p3 = __floats2half2_rn(nh6, nh7);
    uint4 u16;
    u16.x = *reinterpret_cast<uint32_t*>(&p0);
    u16.y = *reinterpret_cast<uint32_t*>(&p1);
    u16.z = *reinterpret_cast<uint32_t*>(&p2);
    u16.w = *reinterpret_cast<uint32_t*>(&p3);
    *reinterpret_cast<uint4*>(g_h16 + hnext) = u16;

    float* op = out + ((size_t)b * T_ + tout) * (2 * H_) + (size_t)d * H_ + j;
    *(float4*)(op)     = make_float4(nh0, nh1, nh2, nh3);
    *(float4*)(op + 4) = make_float4(nh4, nh5, nh6, nh7);
}

// ------------------------------ small kernels ------------------------------
__global__ void cvt16(const float* __restrict__ s, __half* __restrict__ d, int n4)
{
    int i = blockIdx.x * blockDim.x + threadIdx.x;
    if (i < n4) {
        float4 v = reinterpret_cast<const float4*>(s)[i];
        __half2 p0 = __floats2half2_rn(v.x, v.y);
        __half2 p1 = __floats2half2_rn(v.z, v.w);
        uint2 u; u.x = *reinterpret_cast<uint32_t*>(&p0); u.y = *reinterpret_cast<uint32_t*>(&p1);
        reinterpret_cast<uint2*>(d)[i] = u;
    }
}

__global__ void bias_prep(const float* __restrict__ b_izr, const float* __restrict__ b_hzr,
                          const float* __restrict__ b_it,  const float* __restrict__ b_ht)
{
    int j = blockIdx.x * blockDim.x + threadIdx.x;
    if (j < H_) {
        g_br[j]  = b_izr[j] + b_hzr[j];
        g_bz[j]  = b_izr[H_ + j] + b_hzr[H_ + j];
        g_bti[j] = b_it[j];
        g_bth[j] = b_ht[j];
    }
}

__global__ void init_h(const float* __restrict__ h0, const float* __restrict__ bih0)
{
    size_t i = (size_t)blockIdx.x * blockDim.x + threadIdx.x;
    if (i < (size_t)B_ * H_) {
        g_h16[i] = __float2half_rn(h0[i]);                       // dir 0, phase 0
        g_h16[(size_t)2 * B_ * H_ + i] = __float2half_rn(bih0[i]); // dir 1, phase 0
    }
}

// ------------------------------ host side ----------------------------------
extern "C" void kernel_launch(void* const* d_in, const int* in_sizes, int n_in,
                              void* d_out, int out_size)
{
    const float* x     = (const float*)d_in[0];
    const float* h0    = (const float*)d_in[1];
    const float* bih0  = (const float*)d_in[2];
    const float* W_izr = (const float*)d_in[3];
    const float* b_izr = (const float*)d_in[4];
    const float* W_hzr = (const float*)d_in[5];
    const float* b_hzr = (const float*)d_in[6];
    const float* W_it  = (const float*)d_in[7];
    const float* b_it  = (const float*)d_in[8];
    const float* W_ht  = (const float*)d_in[9];
    const float* b_ht  = (const float*)d_in[10];
    float* out = (float*)d_out;
    (void)in_sizes; (void)n_in; (void)out_size;

    void *p_x16 = nullptr, *p_wx = nullptr, *p_wh = nullptr;
    cudaGetSymbolAddress(&p_x16, g_x16);
    cudaGetSymbolAddress(&p_wx, g_wx16);
    cudaGetSymbolAddress(&p_wh, g_wh16);

    cudaFuncSetAttribute(gemm_f16, cudaFuncAttributeMaxDynamicSharedMemorySize, SMEM_BYTES);

    // streams/events created ONCE (deterministic; keeps mem baseline stable)
    static cudaStream_t st2 = nullptr;
    static cudaEvent_t evFork, evPrep2, evGx, evJoin;
    if (st2 == nullptr) {
        cudaStreamCreateWithFlags(&st2, cudaStreamNonBlocking);
        cudaEventCreateWithFlags(&evFork,  cudaEventDisableTiming);
        cudaEventCreateWithFlags(&evPrep2, cudaEventDisableTiming);
        cudaEventCreateWithFlags(&evGx,    cudaEventDisableTiming);
        cudaEventCreateWithFlags(&evJoin,  cudaEventDisableTiming);
    }

    cudaEventRecord(evFork, 0);
    cudaStreamWaitEvent(st2, evFork, 0);

    // prep split across streams
    const int WN4 = 2 * H_ * K_ / 4, WN4b = H_ * K_ / 4, XN4 = B_ * T_ * K_ / 4;
    cvt16<<<(WN4 + 255) / 256, 256>>>(W_izr, (__half*)p_wx, WN4);
    cvt16<<<(WN4b + 255) / 256, 256>>>(W_it, (__half*)p_wx + (size_t)2 * H_ * K_, WN4b);
    cvt16<<<(XN4 + 255) / 256, 256>>>(x, (__half*)p_x16, XN4);
    bias_prep<<<4, 256>>>(b_izr, b_hzr, b_it, b_ht);
    cvt16<<<(WN4 + 255) / 256, 256, 0, st2>>>(W_hzr, (__half*)p_wh, WN4);
    cvt16<<<(WN4b + 255) / 256, 256, 0, st2>>>(W_ht, (__half*)p_wh + (size_t)2 * H_ * K_, WN4b);
    init_h<<<(B_ * H_ + 255) / 256, 256, 0, st2>>>(h0, bih0);
    cudaEventRecord(evPrep2, st2);

    // Gx = X @ [W_izr; W_it]^T over all (b, t)   (stream 0)
    gemm_f16<<<dim3(N3 / BN, (B_ * T_) / BM), 128, SMEM_BYTES>>>(0, 0, 0);
    cudaEventRecord(evGx, 0);

    // stream 0's chain needs wh16/h16 (prep on st2); st2's chain needs Gx+biases
    cudaStreamWaitEvent(0, evPrep2, 0);
    cudaStreamWaitEvent(st2, evGx, 0);

    const int GATE_BLKS = (B_ * H_) / (256 * 8);
    for (int s = 0; s < T_; ++s) {
        gemm_f16<<<dim3(N3 / BN, B_ / BM), 128, SMEM_BYTES>>>(0, s & 1, 1);
        gemm_f16<<<dim3(N3 / BN, B_ / BM), 128, SMEM_BYTES, st2>>>(1, s & 1, 1);
        gate_kernel<<<GATE_BLKS, 256>>>(out, 0, s);
        gate_kernel<<<GATE_BLKS, 256, 0, st2>>>(out, 1, s);
    }

    // join st2 back into the captured stream
    cudaEventRecord(evJoin, st2);
    cudaStreamWaitEvent(0, evJoin, 0);
}